// round 11
// baseline (speedup 1.0000x reference)
#include <cuda_runtime.h>
#include <math.h>

#define BATCH 4
#define NCLS 3
#define HH 96
#define WW 96
#define NPIX (HH * WW)           // 9216
#define NCOMBO 16                // batch(4) x class(2) x dir(2)
#define HCAP 1024                // histogram bins; d^2 >= HCAP -> overflow list
#define THREADS 1024
#define NWARP (THREADS / 32)     // 32
#define NSEG 4
#define SEGROWS (HH / NSEG)      // 24
#define RS 4                     // row-slices per combo
#define SLICEROWS (HH / RS)      // 24
#define SLICEPIX (SLICEROWS * WW)// 2304
#define FULLMASK 0xffffffffu

// cross-kernel state
__device__ int g_hist[NCOMBO][HCAP];           // global histograms (zeroed by prep)
__device__ float g_stats[NCOMBO][3];           // {max, mean, percentile}
__device__ int g_cdone[NCOMBO];                // per-combo slice-done counters
__device__ int g_done;                         // combo-stats-done counter
__device__ int g_ovf_cnt[NCOMBO];
__device__ unsigned short g_ovf[NCOMBO][NPIX]; // overflow d^2 (expected unused)
__device__ unsigned char g_pred[BATCH][NPIX];  // argmax class map
__device__ unsigned char g_lab[BATCH][NPIX];   // label class map

// ---------------------------------------------------------------------------
// Kernel 1 (prep): wide-grid zero + map build. 96 blocks x 256 threads =
// 24576 threads >= every task count -> no loops, max memory-level parallelism.
// ---------------------------------------------------------------------------
#define PREP_BLOCKS 96
#define PREP_THREADS 256

__global__ __launch_bounds__(PREP_THREADS)
void prep_kernel(const float* __restrict__ preds,
                 const int* __restrict__ labels) {
    int t = blockIdx.x * PREP_THREADS + threadIdx.x;
    if (t < NCOMBO * HCAP) (&g_hist[0][0])[t] = 0;
    if (t < NCOMBO) { g_ovf_cnt[t] = 0; g_cdone[t] = 0; }
    if (t == NCOMBO) g_done = 0;

    const int QPB = NPIX / 4;                  // 2304 quads per batch elem
    if (t < BATCH * QPB) {
        int i = t / QPB;
        int q = t - i * QPB;
        const float* base = preds + (size_t)i * NCLS * NPIX;
        float4 a = __ldg((const float4*)base + q);
        float4 b = __ldg((const float4*)(base + NPIX) + q);
        float4 d = __ldg((const float4*)(base + 2 * NPIX) + q);
        int4 L = __ldg((const int4*)(labels + i * NPIX) + q);
        uchar4 pc, lb;
        {
            int k = 0; float bv = a.x;
            if (b.x > bv) { bv = b.x; k = 1; }
            if (d.x > bv) k = 2;
            pc.x = (unsigned char)k;
        }
        {
            int k = 0; float bv = a.y;
            if (b.y > bv) { bv = b.y; k = 1; }
            if (d.y > bv) k = 2;
            pc.y = (unsigned char)k;
        }
        {
            int k = 0; float bv = a.z;
            if (b.z > bv) { bv = b.z; k = 1; }
            if (d.z > bv) k = 2;
            pc.z = (unsigned char)k;
        }
        {
            int k = 0; float bv = a.w;
            if (b.w > bv) { bv = b.w; k = 1; }
            if (d.w > bv) k = 2;
            pc.w = (unsigned char)k;
        }
        lb.x = (unsigned char)L.x; lb.y = (unsigned char)L.y;
        lb.z = (unsigned char)L.z; lb.w = (unsigned char)L.w;
        *(uchar4*)&g_pred[i][q * 4] = pc;
        *(uchar4*)&g_lab[i][q * 4] = lb;
    }
}

// ---------------------------------------------------------------------------
// Kernel 2 (field+stats): 64 blocks = 16 combos x 4 row-slices.
// Cheap column sweeps recomputed per block; merge + pass-2 on its slice;
// warp-aggregated RED.ADD into global per-combo histogram. The LAST slice
// block per combo computes that combo's stats; the last combo assembles out.
//
// Dynamic smem:
//   ushort g[NPIX]         18432 B  (reused as int hist cache in stats phase)
//   uchar  gF[NPIX]         9216 B
//   uchar  gB[NPIX]         9216 B
//   uchar  smapS[NPIX]      9216 B
//   uchar  tmapS[NPIX]      9216 B
//   int    lastSet/firstSet/pmArr/sfArr [4][96] x4 = 6144 B
// ---------------------------------------------------------------------------
#define SMEM_K1 (NPIX * 2 + NPIX * 4 + 4 * NSEG * WW * 4)

__global__ __launch_bounds__(THREADS, 1)
void field_kernel(float* __restrict__ out) {
    extern __shared__ char smem[];
    unsigned short* g = (unsigned short*)smem;
    unsigned char* gF = (unsigned char*)(g + NPIX);
    unsigned char* gB = gF + NPIX;
    unsigned char* smapS = gB + NPIX;
    unsigned char* tmapS = smapS + NPIX;
    int* lastSet = (int*)(tmapS + NPIX);       // [NSEG][WW]
    int* firstSet = lastSet + NSEG * WW;
    int* pmArr = firstSet + NSEG * WW;
    int* sfArr = pmArr + NSEG * WW;
    int* sh_hist = (int*)smem;                 // stats phase only (reuses g)

    __shared__ int s_n[NWARP];
    __shared__ float s_sum[NWARP];
    __shared__ int s_mx[NWARP];
    __shared__ int s_cl;    // last slice block of this combo?
    __shared__ int s_last;  // last combo overall?

    const int c = blockIdx.x / RS;
    const int slice = blockIdx.x - c * RS;
    const int i = c >> 2;
    const int j = ((c >> 1) & 1) + 1;
    const int dir = c & 1;
    const int tid = threadIdx.x;
    const int lane = tid & 31;
    const int wid = tid >> 5;

    // copy byte maps from global (L2-hot) into smem, uint4 = 16 B/thread, 1 iter
    {
        const uint4* sm = (const uint4*)(dir == 0 ? g_pred[i] : g_lab[i]);
        const uint4* tm = (const uint4*)(dir == 0 ? g_lab[i] : g_pred[i]);
        uint4* ds = (uint4*)smapS;
        uint4* dt = (uint4*)tmapS;
        for (int q = tid; q < NPIX / 16; q += THREADS) {
            ds[q] = __ldg(&sm[q]);
            dt[q] = __ldg(&tm[q]);
        }
    }
    __syncthreads();

    // pass 1: 4-way segmented per-column 1-D sweeps (768 tasks, 24 iters)
    if (tid < 2 * NSEG * WW) {
        const int col = tid % WW;
        const int seg = (tid / WW) & (NSEG - 1);
        const int dirIdx = tid / (NSEG * WW);
        const int r0 = seg * SEGROWS;
        if (dirIdx == 0) {              // forward (top -> down)
            int last = -1000;
            #pragma unroll 4
            for (int k = 0; k < SEGROWS; k++) {
                int r = r0 + k;
                if (tmapS[r * WW + col] == j) last = r;
                gF[r * WW + col] = (unsigned char)min(r - last, 255);
            }
            lastSet[seg * WW + col] = last;
        } else {                        // backward (bottom -> up)
            int first = 1000;
            #pragma unroll 4
            for (int k = SEGROWS - 1; k >= 0; k--) {
                int r = r0 + k;
                if (tmapS[r * WW + col] == j) first = r;
                gB[r * WW + col] = (unsigned char)min(first - r, 255);
            }
            firstSet[seg * WW + col] = first;
        }
    }
    __syncthreads();

    // per-column prefix-max of lastSet / suffix-min of firstSet (4 iters)
    if (tid < WW) {
        const int col = tid;
        int pm = -1000;
        #pragma unroll
        for (int s = 0; s < NSEG; s++) {
            pmArr[s * WW + col] = pm;
            pm = max(pm, lastSet[s * WW + col]);
        }
    } else if (tid < 2 * WW) {
        const int col = tid - WW;
        int fm = 1000;
        #pragma unroll
        for (int s = NSEG - 1; s >= 0; s--) {
            sfArr[s * WW + col] = fm;
            fm = min(fm, firstSet[s * WW + col]);
        }
    }
    __syncthreads();

    const int p0 = slice * SLICEPIX;

    // merge: exact 1-D column distance for slice rows only (2.25 iters)
    for (int p = p0 + tid; p < p0 + SLICEPIX; p += THREADS) {
        int r = p / WW;
        int cc = p - r * WW;
        int s = r / SEGROWS;
        int d = min((int)gF[p], (int)gB[p]);
        d = min(d, r - pmArr[s * WW + cc]);
        d = min(d, sfArr[s * WW + cc] - r);
        d = min(d, 255);
        g[p] = (unsigned short)(d * d);
    }
    __syncthreads();

    // pass 2: slice rows only (warp-uniform trip count per warp -> match_any ok)
    for (int p = p0 + tid; p < p0 + SLICEPIX; p += THREADS) {
        int r = p / WW;
        int cc = p - r * WW;
        bool valid = (smapS[p] == j);
        int best = -1;
        if (valid) {
            const unsigned short* grow = g + r * WW;
            best = grow[cc];
            if (best > 1) {
                int v;
                v = 1 + ((cc - 1 >= 0) ? (int)grow[cc - 1] : 0x7fff); best = min(best, v);
                v = 1 + ((cc + 1 < WW) ? (int)grow[cc + 1] : 0x7fff); best = min(best, v);
                v = 4 + ((cc - 2 >= 0) ? (int)grow[cc - 2] : 0x7fff); best = min(best, v);
                v = 4 + ((cc + 2 < WW) ? (int)grow[cc + 2] : 0x7fff); best = min(best, v);
                v = 9 + ((cc - 3 >= 0) ? (int)grow[cc - 3] : 0x7fff); best = min(best, v);
                v = 9 + ((cc + 3 < WW) ? (int)grow[cc + 3] : 0x7fff); best = min(best, v);
                for (int dc = 4; dc < WW; dc++) {
                    int d2 = dc * dc;
                    if (d2 >= best) break;
                    int cl = cc - dc, cr = cc + dc;
                    if (cl >= 0) { int vv = d2 + (int)grow[cl]; if (vv < best) best = vv; }
                    if (cr < WW) { int vv = d2 + (int)grow[cr]; if (vv < best) best = vv; }
                }
            }
        }
        // warp-aggregate equal bins: one global RED per distinct value per warp
        unsigned grp = __match_any_sync(FULLMASK, best);
        if (valid) {
            if (best < HCAP) {
                if (lane == __ffs(grp) - 1) atomicAdd(&g_hist[c][best], __popc(grp));
            } else {
                int pos = atomicAdd(&g_ovf_cnt[c], 1);
                g_ovf[c][pos] = (unsigned short)min(best, 65535);
            }
        }
    }
    __syncthreads();

    // ---- combo completion: last of RS slice blocks computes this combo's stats
    if (tid == 0) {
        __threadfence();
        int t = atomicAdd(&g_cdone[c], 1);
        s_cl = (t == RS - 1) ? 1 : 0;
    }
    __syncthreads();
    if (!s_cl) return;

    // stats phase (histogram complete for combo c). Bypass L1 for atomics' data.
    int h = __ldcg(&g_hist[c][tid]);           // 1 iter (HCAP == THREADS)
    sh_hist[tid] = h;
    int n_loc = h;
    float sum_loc = h ? (float)h * sqrtf((float)tid) : 0.f;
    int mx_loc = h ? tid : 0;
    #pragma unroll
    for (int off = 16; off; off >>= 1) {
        n_loc += __shfl_down_sync(FULLMASK, n_loc, off);
        sum_loc += __shfl_down_sync(FULLMASK, sum_loc, off);
        mx_loc = max(mx_loc, __shfl_down_sync(FULLMASK, mx_loc, off));
    }
    if (lane == 0) { s_n[wid] = n_loc; s_sum[wid] = sum_loc; s_mx[wid] = mx_loc; }
    __syncthreads();
    if (wid == 0) {
        int n2 = s_n[lane];
        float sm2 = s_sum[lane];
        int mx2 = s_mx[lane];
        #pragma unroll
        for (int off = 16; off; off >>= 1) {
            n2 += __shfl_down_sync(FULLMASK, n2, off);
            sm2 += __shfl_down_sync(FULLMASK, sm2, off);
            mx2 = max(mx2, __shfl_down_sync(FULLMASK, mx2, off));
        }
        if (lane == 0) { s_n[0] = n2; s_sum[0] = sm2; s_mx[0] = mx2; }
    }
    __syncthreads();

    // warp 0 cooperative percentile scan, lane 0 finishes
    if (wid == 0) {
        const int n_hist = s_n[0];
        const int maxd2 = s_mx[0];
        const int m = g_ovf_cnt[c];      // overflow entries (expected 0)
        const int n = n_hist + m;
        float vlo = 0.f, vhi = 0.f;
        int lo = 0, hi = 0;
        float frac = 0.f;
        bool gotlo = false, gothi = false;
        if (n > 0) {
            float pos = 0.95f * (float)(n - 1);
            lo = (int)floorf(pos);
            hi = (int)ceilf(pos);
            frac = pos - (float)lo;
            int base = 0;
            for (int b0 = 0; b0 <= maxd2 && !gothi; b0 += 32) {
                int bb = b0 + lane;
                int hh = (bb < HCAP) ? sh_hist[bb] : 0;
                int cum = hh;
                #pragma unroll
                for (int off = 1; off < 32; off <<= 1) {
                    int v = __shfl_up_sync(FULLMASK, cum, off);
                    if (lane >= off) cum += v;
                }
                int ct = base + cum;
                unsigned mlo = __ballot_sync(FULLMASK, ct > lo);
                if (!gotlo && mlo) { vlo = sqrtf((float)(b0 + __ffs(mlo) - 1)); gotlo = true; }
                unsigned mhi = __ballot_sync(FULLMASK, ct > hi);
                if (!gothi && mhi) { vhi = sqrtf((float)(b0 + __ffs(mhi) - 1)); gothi = true; }
                base += __shfl_sync(FULLMASK, cum, 31);
            }
        }
        if (lane == 0) {
            float sum = s_sum[0];
            if (m > 0) {                 // exact slow path, correctness only
                for (int a = 0; a < m - 1; a++) {
                    int mi = a;
                    for (int b = a + 1; b < m; b++)
                        if (g_ovf[c][b] < g_ovf[c][mi]) mi = b;
                    unsigned short t = g_ovf[c][a];
                    g_ovf[c][a] = g_ovf[c][mi];
                    g_ovf[c][mi] = t;
                }
                for (int a = 0; a < m; a++) sum += sqrtf((float)g_ovf[c][a]);
            }
            float mx = 0.f, mean = 0.f, pcl = 0.f;
            if (n > 0) {
                int truemax = (m > 0) ? (int)g_ovf[c][m - 1] : maxd2;
                mx = sqrtf((float)truemax);
                mean = sum / (float)n;
                if (!gotlo) vlo = sqrtf((float)g_ovf[c][lo - n_hist]);
                if (!gothi) vhi = sqrtf((float)g_ovf[c][hi - n_hist]);
                pcl = vlo * (1.0f - frac) + vhi * frac;
            }
            g_stats[c][0] = mx;
            g_stats[c][1] = mean;
            g_stats[c][2] = pcl;
            __threadfence();
            int t = atomicAdd(&g_done, 1);
            s_last = (t == NCOMBO - 1) ? 1 : 0;
        }
    }
    __syncthreads();

    // last combo assembles the output
    if (s_last && tid == 0) {
        __threadfence();
        float st[NCOMBO * 3];
        #pragma unroll
        for (int k = 0; k < NCOMBO * 3; k++)
            st[k] = *((volatile float*)&g_stats[0][0] + k);
        float M[3][5] = {{0}}, F[3][5] = {{0}}, R[3][5] = {{0}};
        for (int bi = 0; bi < BATCH; bi++) {
            for (int jj = 0; jj < 2; jj++) {
                int jc = jj + 1;
                int cf = (bi << 2) | (jj << 1);
                int cr = cf | 1;
                float fmx = st[cf * 3 + 0], rmx = st[cr * 3 + 0];
                float fme = st[cf * 3 + 1], rme = st[cr * 3 + 1];
                float fp  = st[cf * 3 + 2], rp  = st[cr * 3 + 2];
                F[0][jc] += fmx; R[0][jc] += rmx; M[0][jc] += fmaxf(fmx, rmx);
                F[1][jc] += fme; R[1][jc] += rme; M[1][jc] += fmaxf(fme, rme);
                // faithful to source bug: FHD gets both directions' percentiles,
                // RHD percentile row stays zero
                F[2][jc] += fp + rp;
                M[2][jc] += fmaxf(fp, rp);
            }
        }
        float* mats[3] = {&M[0][0], &F[0][0], &R[0][0]};
        for (int t2 = 0; t2 < 3; t2++) {
            float* X = mats[t2];
            for (int r = 0; r < 3; r++) {
                for (int c2 = 0; c2 < 3; c2++) X[r * 5 + c2] *= 0.25f;  // / batch
                X[r * 5 + 3] = (X[r * 5 + 0] + X[r * 5 + 1] + X[r * 5 + 2]) / 3.0f;
                X[r * 5 + 4] = (X[r * 5 + 1] + X[r * 5 + 2]) * 0.5f;
            }
            for (int k = 0; k < 15; k++) out[t2 * 15 + k] = X[k];
        }
    }
}

// ---------------------------------------------------------------------------
extern "C" void kernel_launch(void* const* d_in, const int* in_sizes, int n_in,
                              void* d_out, int out_size) {
    const float* preds = (const float*)d_in[0];
    const int* labels = (const int*)d_in[1];
    float* out = (float*)d_out;

    cudaFuncSetAttribute(field_kernel,
                         cudaFuncAttributeMaxDynamicSharedMemorySize, SMEM_K1);

    prep_kernel<<<PREP_BLOCKS, PREP_THREADS>>>(preds, labels);
    field_kernel<<<NCOMBO * RS, THREADS, SMEM_K1>>>(out);
}

// round 12
// speedup vs baseline: 1.0467x; 1.0467x over previous
#include <cuda_runtime.h>
#include <math.h>

#define BATCH 4
#define NCLS 3
#define HH 96
#define WW 96
#define NPIX (HH * WW)           // 9216
#define NCOMBO 16                // batch(4) x class(2) x dir(2)
#define HCAP 1024                // histogram bins; d^2 >= HCAP -> overflow list
#define THREADS 1024
#define NWARP (THREADS / 32)     // 32
#define NSEG 4
#define SEGROWS (HH / NSEG)      // 24
#define RS 4                     // row-slices per combo
#define SLICEROWS (HH / RS)      // 24
#define SLICEPIX (SLICEROWS * WW)// 2304
#define FULLMASK 0xffffffffu

// cross-kernel state
__device__ int g_hist[NCOMBO][HCAP];           // global histograms (zeroed by prep)
__device__ float g_stats[NCOMBO][3];           // {max, mean, percentile}
__device__ int g_done;                         // last-block-done counter
__device__ int g_ovf_cnt[NCOMBO];
__device__ unsigned short g_ovf[NCOMBO][NPIX]; // overflow d^2 (expected unused)
__device__ unsigned char g_pred[BATCH][NPIX];  // argmax class map
__device__ unsigned char g_lab[BATCH][NPIX];   // label class map

// ---------------------------------------------------------------------------
// Kernel 1 (prep): wide-grid zero + map build. 96 blocks x 256 threads =
// 24576 threads >= every task count -> no loops, max memory-level parallelism.
// ---------------------------------------------------------------------------
#define PREP_BLOCKS 96
#define PREP_THREADS 256

__global__ __launch_bounds__(PREP_THREADS)
void prep_kernel(const float* __restrict__ preds,
                 const int* __restrict__ labels) {
    int t = blockIdx.x * PREP_THREADS + threadIdx.x;
    if (t < NCOMBO * HCAP) (&g_hist[0][0])[t] = 0;
    if (t < NCOMBO) g_ovf_cnt[t] = 0;
    if (t == NCOMBO) g_done = 0;

    const int QPB = NPIX / 4;                  // 2304 quads per batch elem
    if (t < BATCH * QPB) {
        int i = t / QPB;
        int q = t - i * QPB;
        const float* base = preds + (size_t)i * NCLS * NPIX;
        float4 a = __ldg((const float4*)base + q);
        float4 b = __ldg((const float4*)(base + NPIX) + q);
        float4 d = __ldg((const float4*)(base + 2 * NPIX) + q);
        int4 L = __ldg((const int4*)(labels + i * NPIX) + q);
        uchar4 pc, lb;
        {
            int k = 0; float bv = a.x;
            if (b.x > bv) { bv = b.x; k = 1; }
            if (d.x > bv) k = 2;
            pc.x = (unsigned char)k;
        }
        {
            int k = 0; float bv = a.y;
            if (b.y > bv) { bv = b.y; k = 1; }
            if (d.y > bv) k = 2;
            pc.y = (unsigned char)k;
        }
        {
            int k = 0; float bv = a.z;
            if (b.z > bv) { bv = b.z; k = 1; }
            if (d.z > bv) k = 2;
            pc.z = (unsigned char)k;
        }
        {
            int k = 0; float bv = a.w;
            if (b.w > bv) { bv = b.w; k = 1; }
            if (d.w > bv) k = 2;
            pc.w = (unsigned char)k;
        }
        lb.x = (unsigned char)L.x; lb.y = (unsigned char)L.y;
        lb.z = (unsigned char)L.z; lb.w = (unsigned char)L.w;
        *(uchar4*)&g_pred[i][q * 4] = pc;
        *(uchar4*)&g_lab[i][q * 4] = lb;
    }
}

// ---------------------------------------------------------------------------
// Kernel 2 (field): 64 blocks = 16 combos x 4 row-slices.
// Recomputes cheap column sweeps per block; merge + pass-2 only on its slice;
// warp-aggregated RED.ADD into the global per-combo histogram.
//
// Dynamic smem:
//   ushort g[NPIX]         18432 B  (only slice rows written/read)
//   uchar  gF[NPIX]         9216 B
//   uchar  gB[NPIX]         9216 B
//   uchar  smapS[NPIX]      9216 B
//   uchar  tmapS[NPIX]      9216 B
//   int    lastSet/firstSet/pmArr/sfArr [4][96] x4 = 6144 B
// ---------------------------------------------------------------------------
#define SMEM_K1 (NPIX * 2 + NPIX * 4 + 4 * NSEG * WW * 4)

__global__ __launch_bounds__(THREADS, 1)
void field_kernel() {
    extern __shared__ char smem[];
    unsigned short* g = (unsigned short*)smem;
    unsigned char* gF = (unsigned char*)(g + NPIX);
    unsigned char* gB = gF + NPIX;
    unsigned char* smapS = gB + NPIX;
    unsigned char* tmapS = smapS + NPIX;
    int* lastSet = (int*)(tmapS + NPIX);       // [NSEG][WW]
    int* firstSet = lastSet + NSEG * WW;
    int* pmArr = firstSet + NSEG * WW;
    int* sfArr = pmArr + NSEG * WW;

    const int c = blockIdx.x / RS;
    const int slice = blockIdx.x - c * RS;
    const int i = c >> 2;
    const int j = ((c >> 1) & 1) + 1;
    const int dir = c & 1;
    const int tid = threadIdx.x;
    const int lane = tid & 31;

    // copy byte maps from global (L2-hot) into smem, uint4 = 16 B/thread, 1 iter
    {
        const uint4* sm = (const uint4*)(dir == 0 ? g_pred[i] : g_lab[i]);
        const uint4* tm = (const uint4*)(dir == 0 ? g_lab[i] : g_pred[i]);
        uint4* ds = (uint4*)smapS;
        uint4* dt = (uint4*)tmapS;
        for (int q = tid; q < NPIX / 16; q += THREADS) {
            ds[q] = __ldg(&sm[q]);
            dt[q] = __ldg(&tm[q]);
        }
    }
    __syncthreads();

    // pass 1: 4-way segmented per-column 1-D sweeps (768 tasks, 24 iters)
    if (tid < 2 * NSEG * WW) {
        const int col = tid % WW;
        const int seg = (tid / WW) & (NSEG - 1);
        const int dirIdx = tid / (NSEG * WW);
        const int r0 = seg * SEGROWS;
        if (dirIdx == 0) {              // forward (top -> down)
            int last = -1000;
            #pragma unroll 4
            for (int k = 0; k < SEGROWS; k++) {
                int r = r0 + k;
                if (tmapS[r * WW + col] == j) last = r;
                gF[r * WW + col] = (unsigned char)min(r - last, 255);
            }
            lastSet[seg * WW + col] = last;
        } else {                        // backward (bottom -> up)
            int first = 1000;
            #pragma unroll 4
            for (int k = SEGROWS - 1; k >= 0; k--) {
                int r = r0 + k;
                if (tmapS[r * WW + col] == j) first = r;
                gB[r * WW + col] = (unsigned char)min(first - r, 255);
            }
            firstSet[seg * WW + col] = first;
        }
    }
    __syncthreads();

    // per-column prefix-max of lastSet / suffix-min of firstSet (4 iters)
    if (tid < WW) {
        const int col = tid;
        int pm = -1000;
        #pragma unroll
        for (int s = 0; s < NSEG; s++) {
            pmArr[s * WW + col] = pm;
            pm = max(pm, lastSet[s * WW + col]);
        }
    } else if (tid < 2 * WW) {
        const int col = tid - WW;
        int fm = 1000;
        #pragma unroll
        for (int s = NSEG - 1; s >= 0; s--) {
            sfArr[s * WW + col] = fm;
            fm = min(fm, firstSet[s * WW + col]);
        }
    }
    __syncthreads();

    const int p0 = slice * SLICEPIX;

    // merge: exact 1-D column distance for slice rows only (2.25 iters)
    for (int p = p0 + tid; p < p0 + SLICEPIX; p += THREADS) {
        int r = p / WW;
        int cc = p - r * WW;
        int s = r / SEGROWS;
        int d = min((int)gF[p], (int)gB[p]);
        d = min(d, r - pmArr[s * WW + cc]);
        d = min(d, sfArr[s * WW + cc] - r);
        d = min(d, 255);
        g[p] = (unsigned short)(d * d);
    }
    __syncthreads();

    // pass 2: slice rows only (warp-uniform trip count -> match_any legal)
    for (int p = p0 + tid; p < p0 + SLICEPIX; p += THREADS) {
        int r = p / WW;
        int cc = p - r * WW;
        bool valid = (smapS[p] == j);
        int best = -1;
        if (valid) {
            const unsigned short* grow = g + r * WW;
            best = grow[cc];
            if (best > 1) {
                int v;
                v = 1 + ((cc - 1 >= 0) ? (int)grow[cc - 1] : 0x7fff); best = min(best, v);
                v = 1 + ((cc + 1 < WW) ? (int)grow[cc + 1] : 0x7fff); best = min(best, v);
                v = 4 + ((cc - 2 >= 0) ? (int)grow[cc - 2] : 0x7fff); best = min(best, v);
                v = 4 + ((cc + 2 < WW) ? (int)grow[cc + 2] : 0x7fff); best = min(best, v);
                v = 9 + ((cc - 3 >= 0) ? (int)grow[cc - 3] : 0x7fff); best = min(best, v);
                v = 9 + ((cc + 3 < WW) ? (int)grow[cc + 3] : 0x7fff); best = min(best, v);
                for (int dc = 4; dc < WW; dc++) {
                    int d2 = dc * dc;
                    if (d2 >= best) break;
                    int cl = cc - dc, cr = cc + dc;
                    if (cl >= 0) { int vv = d2 + (int)grow[cl]; if (vv < best) best = vv; }
                    if (cr < WW) { int vv = d2 + (int)grow[cr]; if (vv < best) best = vv; }
                }
            }
        }
        // warp-aggregate equal bins: one global RED per distinct value per warp
        unsigned grp = __match_any_sync(FULLMASK, best);
        if (valid) {
            if (best < HCAP) {
                if (lane == __ffs(grp) - 1) atomicAdd(&g_hist[c][best], __popc(grp));
            } else {
                int pos = atomicAdd(&g_ovf_cnt[c], 1);
                g_ovf[c][pos] = (unsigned short)min(best, 65535);
            }
        }
    }
}

// ---------------------------------------------------------------------------
// Kernel 3 (stats): one block per combo; last finishing block assembles output.
// ---------------------------------------------------------------------------
__global__ __launch_bounds__(THREADS, 1)
void stats_kernel(float* __restrict__ out) {
    __shared__ int sh_hist[HCAP];
    __shared__ int s_n[NWARP];
    __shared__ float s_sum[NWARP];
    __shared__ int s_mx[NWARP];
    __shared__ int s_last;

    const int c = blockIdx.x;
    const int tid = threadIdx.x;
    const int lane = tid & 31;
    const int wid = tid >> 5;

    int h = __ldg(&g_hist[c][tid]);            // 1 iter (HCAP == THREADS)
    sh_hist[tid] = h;
    int n_loc = h;
    float sum_loc = h ? (float)h * sqrtf((float)tid) : 0.f;
    int mx_loc = h ? tid : 0;
    #pragma unroll
    for (int off = 16; off; off >>= 1) {
        n_loc += __shfl_down_sync(FULLMASK, n_loc, off);
        sum_loc += __shfl_down_sync(FULLMASK, sum_loc, off);
        mx_loc = max(mx_loc, __shfl_down_sync(FULLMASK, mx_loc, off));
    }
    if (lane == 0) { s_n[wid] = n_loc; s_sum[wid] = sum_loc; s_mx[wid] = mx_loc; }
    __syncthreads();
    if (wid == 0) {
        int n2 = s_n[lane];
        float sm2 = s_sum[lane];
        int mx2 = s_mx[lane];
        #pragma unroll
        for (int off = 16; off; off >>= 1) {
            n2 += __shfl_down_sync(FULLMASK, n2, off);
            sm2 += __shfl_down_sync(FULLMASK, sm2, off);
            mx2 = max(mx2, __shfl_down_sync(FULLMASK, mx2, off));
        }
        if (lane == 0) { s_n[0] = n2; s_sum[0] = sm2; s_mx[0] = mx2; }
    }
    __syncthreads();

    // warp 0 cooperative percentile scan, lane 0 finishes
    if (wid == 0) {
        const int n_hist = s_n[0];
        const int maxd2 = s_mx[0];
        const int m = g_ovf_cnt[c];      // overflow entries (expected 0)
        const int n = n_hist + m;
        float vlo = 0.f, vhi = 0.f;
        int lo = 0, hi = 0;
        float frac = 0.f;
        bool gotlo = false, gothi = false;
        if (n > 0) {
            float pos = 0.95f * (float)(n - 1);
            lo = (int)floorf(pos);
            hi = (int)ceilf(pos);
            frac = pos - (float)lo;
            int base = 0;
            for (int b0 = 0; b0 <= maxd2 && !gothi; b0 += 32) {
                int bb = b0 + lane;
                int hh = (bb < HCAP) ? sh_hist[bb] : 0;
                int cum = hh;
                #pragma unroll
                for (int off = 1; off < 32; off <<= 1) {
                    int v = __shfl_up_sync(FULLMASK, cum, off);
                    if (lane >= off) cum += v;
                }
                int ct = base + cum;
                unsigned mlo = __ballot_sync(FULLMASK, ct > lo);
                if (!gotlo && mlo) { vlo = sqrtf((float)(b0 + __ffs(mlo) - 1)); gotlo = true; }
                unsigned mhi = __ballot_sync(FULLMASK, ct > hi);
                if (!gothi && mhi) { vhi = sqrtf((float)(b0 + __ffs(mhi) - 1)); gothi = true; }
                base += __shfl_sync(FULLMASK, cum, 31);
            }
        }
        if (lane == 0) {
            float sum = s_sum[0];
            if (m > 0) {                 // exact slow path, correctness only
                for (int a = 0; a < m - 1; a++) {
                    int mi = a;
                    for (int b = a + 1; b < m; b++)
                        if (g_ovf[c][b] < g_ovf[c][mi]) mi = b;
                    unsigned short t = g_ovf[c][a];
                    g_ovf[c][a] = g_ovf[c][mi];
                    g_ovf[c][mi] = t;
                }
                for (int a = 0; a < m; a++) sum += sqrtf((float)g_ovf[c][a]);
            }
            float mx = 0.f, mean = 0.f, pcl = 0.f;
            if (n > 0) {
                int truemax = (m > 0) ? (int)g_ovf[c][m - 1] : maxd2;
                mx = sqrtf((float)truemax);
                mean = sum / (float)n;
                if (!gotlo) vlo = sqrtf((float)g_ovf[c][lo - n_hist]);
                if (!gothi) vhi = sqrtf((float)g_ovf[c][hi - n_hist]);
                pcl = vlo * (1.0f - frac) + vhi * frac;
            }
            g_stats[c][0] = mx;
            g_stats[c][1] = mean;
            g_stats[c][2] = pcl;
            __threadfence();
            int t = atomicAdd(&g_done, 1);
            s_last = (t == NCOMBO - 1) ? 1 : 0;
        }
    }
    __syncthreads();

    // last block assembles the output
    if (s_last && tid == 0) {
        __threadfence();
        float st[NCOMBO * 3];
        #pragma unroll
        for (int k = 0; k < NCOMBO * 3; k++)
            st[k] = *((volatile float*)&g_stats[0][0] + k);
        float M[3][5] = {{0}}, F[3][5] = {{0}}, R[3][5] = {{0}};
        for (int bi = 0; bi < BATCH; bi++) {
            for (int jj = 0; jj < 2; jj++) {
                int jc = jj + 1;
                int cf = (bi << 2) | (jj << 1);
                int cr = cf | 1;
                float fmx = st[cf * 3 + 0], rmx = st[cr * 3 + 0];
                float fme = st[cf * 3 + 1], rme = st[cr * 3 + 1];
                float fp  = st[cf * 3 + 2], rp  = st[cr * 3 + 2];
                F[0][jc] += fmx; R[0][jc] += rmx; M[0][jc] += fmaxf(fmx, rmx);
                F[1][jc] += fme; R[1][jc] += rme; M[1][jc] += fmaxf(fme, rme);
                // faithful to source bug: FHD gets both directions' percentiles,
                // RHD percentile row stays zero
                F[2][jc] += fp + rp;
                M[2][jc] += fmaxf(fp, rp);
            }
        }
        float* mats[3] = {&M[0][0], &F[0][0], &R[0][0]};
        for (int t2 = 0; t2 < 3; t2++) {
            float* X = mats[t2];
            for (int r = 0; r < 3; r++) {
                for (int c2 = 0; c2 < 3; c2++) X[r * 5 + c2] *= 0.25f;  // / batch
                X[r * 5 + 3] = (X[r * 5 + 0] + X[r * 5 + 1] + X[r * 5 + 2]) / 3.0f;
                X[r * 5 + 4] = (X[r * 5 + 1] + X[r * 5 + 2]) * 0.5f;
            }
            for (int k = 0; k < 15; k++) out[t2 * 15 + k] = X[k];
        }
    }
}

// ---------------------------------------------------------------------------
extern "C" void kernel_launch(void* const* d_in, const int* in_sizes, int n_in,
                              void* d_out, int out_size) {
    const float* preds = (const float*)d_in[0];
    const int* labels = (const int*)d_in[1];
    float* out = (float*)d_out;

    cudaFuncSetAttribute(field_kernel,
                         cudaFuncAttributeMaxDynamicSharedMemorySize, SMEM_K1);

    prep_kernel<<<PREP_BLOCKS, PREP_THREADS>>>(preds, labels);
    field_kernel<<<NCOMBO * RS, THREADS, SMEM_K1>>>();
    stats_kernel<<<NCOMBO, THREADS>>>(out);
}